// round 16
// baseline (speedup 1.0000x reference)
#include <cuda_runtime.h>
#include <cuda_bf16.h>
#include <cstdint>

#define NN   524288
#define BSEG 4096
#define SEG  128
#define DIN  128
#define HH   256

// Static device scratch (alloc-free rules).
// Packed k-pair bf16 hi/lo: uint2 = (hi0|hi1<<16, lo0|lo1<<16)
__device__ uint2 g_hp1[(size_t)NN * (HH / 2)];
__device__ uint2 g_hp2[(size_t)NN * (HH / 2)];
__device__ float g_part[(size_t)16 * NN];         // fused logit partials (16 slots)
__device__ uint2 g_wp0[(size_t)(DIN / 2) * HH];   // pre-split weights
__device__ uint2 g_wp1[(size_t)(HH / 2) * HH];
__device__ uint2 g_wp2[(size_t)(HH / 2) * HH];

// ---------------------------------------------------------------------------
// bf16 two-term split: x ~= hi + lo, repr error ~2^-18 |x|.
// ---------------------------------------------------------------------------
__device__ __forceinline__ void bsplit(float x, uint32_t& h, uint32_t& l) {
    __nv_bfloat16 bh = __float2bfloat16_rn(x);
    float r = x - __bfloat162float(bh);
    __nv_bfloat16 bl = __float2bfloat16_rn(r);
    h = (uint32_t)__bfloat16_as_ushort(bh);
    l = (uint32_t)__bfloat16_as_ushort(bl);
}
__device__ __forceinline__ uint2 pack2(float x0, float x1) {
    uint32_t h0, l0, h1, l1;
    bsplit(x0, h0, l0); bsplit(x1, h1, l1);
    return make_uint2(h0 | (h1 << 16), l0 | (l1 << 16));
}

// One fused prep kernel: split W0, W1, W2 into k-pair-packed uint2 planes.
#define W0_ELEMS ((DIN / 2) * HH)
#define W12_ELEMS ((HH / 2) * HH)
__global__ void split_w_all(const float* __restrict__ W0, const float* __restrict__ W1,
                            const float* __restrict__ W2, uint2* __restrict__ o0,
                            uint2* __restrict__ o1, uint2* __restrict__ o2) {
    int idx = blockIdx.x * blockDim.x + threadIdx.x;
    const float* W; uint2* o; int rel;
    if (idx < W0_ELEMS)                 { W = W0; o = o0; rel = idx; }
    else if (idx < W0_ELEMS + W12_ELEMS){ W = W1; o = o1; rel = idx - W0_ELEMS; }
    else if (idx < W0_ELEMS + 2 * W12_ELEMS) { W = W2; o = o2; rel = idx - W0_ELEMS - W12_ELEMS; }
    else return;
    int kp = rel / HH, n = rel % HH;
    o[rel] = pack2(W[(size_t)(2 * kp) * HH + n], W[(size_t)(2 * kp + 1) * HH + n]);
}

__device__ __forceinline__ void mma16(float* c, const uint32_t* a, uint32_t b0, uint32_t b1) {
    asm volatile("mma.sync.aligned.m16n8k16.row.col.f32.bf16.bf16.f32 "
        "{%0,%1,%2,%3}, {%4,%5,%6,%7}, {%8,%9}, {%0,%1,%2,%3};"
        : "+f"(c[0]), "+f"(c[1]), "+f"(c[2]), "+f"(c[3])
        : "r"(a[0]), "r"(a[1]), "r"(a[2]), "r"(a[3]), "r"(b0), "r"(b1));
}

// cp.async helpers (16B .cg)
__device__ __forceinline__ void cp16(void* smem_dst, const void* gsrc) {
    uint32_t d = (uint32_t)__cvta_generic_to_shared(smem_dst);
    asm volatile("cp.async.cg.shared.global [%0], [%1], 16;" :: "r"(d), "l"(gsrc));
}
__device__ __forceinline__ void cp_commit() { asm volatile("cp.async.commit_group;"); }
template<int NWAIT>
__device__ __forceinline__ void cp_wait() { asm volatile("cp.async.wait_group %0;" :: "n"(NWAIT)); }

// ---------------------------------------------------------------------------
// bf16x3 tensor-core layer, OCCUPANCY variant: block 128(M) x 64(N), BK=32,
// 8 warps (wm 0..1 x wn 0..3), warp tile 64x16, 3 CTAs/SM (24 warps/SM).
// acc = 32 regs, A frags 32, B jit 4 -> ~80 live < 85-reg cap, no spills.
// ---------------------------------------------------------------------------
template<int HIN, bool AFP32, bool FUSE>
__global__ void __launch_bounds__(256, 3) gemm_bf16x3(
    const void* __restrict__ Ain, const uint2* __restrict__ Wp,
    const float* __restrict__ bias, const float* __restrict__ Wf,
    uint2* __restrict__ C)
{
    __shared__ uint2 As[2][128][20];   // [buf][row][kpair], pad 20 (conflict-free)
    __shared__ uint2 Bs[2][16][68];    // [buf][kpair][n 0..63], pad 68

    const int t    = threadIdx.x;
    const int lane = t & 31;
    const int w    = t >> 5;
    const int wm   = w >> 2;          // 0..1 (64 rows each)
    const int wn   = w & 3;           // 0..3 (16 cols each)
    const int row0 = blockIdx.y * 128;
    const int col0 = blockIdx.x * 64;

    const int ar   = t >> 1;          // A row (one row per 2 threads)
    const int ako2 = (t & 1) * 8;     // kpair offset 0 / 8
    const int bkp  = t >> 4;          // B kpair row 0..15
    const int bn0  = (t & 15) * 4;    // B col group

    constexpr int NCH = HIN / 32;

    auto prefetchB = [&](int c, int buf) {
        const uint2* src = Wp + (size_t)(c * 16 + bkp) * HH + col0 + bn0;
        cp16(&Bs[buf][bkp][bn0],     src);
        cp16(&Bs[buf][bkp][bn0 + 2], src + 2);
    };
    auto stageA = [&](int c, int buf) {
        if (AFP32) {
            const float* src = (const float*)Ain + (size_t)(row0 + ar) * HIN + c * 32 + (t & 1) * 16;
#pragma unroll
            for (int q = 0; q < 4; q++) {
                float4 v = *(const float4*)(src + q * 4);
                uint2 a = pack2(v.x, v.y);
                uint2 b = pack2(v.z, v.w);
                *(uint4*)&As[buf][ar][ako2 + q * 2] = make_uint4(a.x, a.y, b.x, b.y);
            }
        } else {
            const uint2* a = (const uint2*)Ain + (size_t)(row0 + ar) * (HIN / 2) + c * 16 + ako2;
#pragma unroll
            for (int q = 0; q < 4; q++)
                cp16(&As[buf][ar][ako2 + q * 2], a + q * 2);
        }
    };

    float acc[4][2][4];
#pragma unroll
    for (int i = 0; i < 4; i++)
#pragma unroll
        for (int j = 0; j < 2; j++)
#pragma unroll
            for (int q = 0; q < 4; q++) acc[i][j][q] = 0.f;

    uint32_t ahi[4][4], alo[4][4];

    const int afr = wm * 64 + (lane >> 2);
    const int afc = lane & 3;
    const int bfn = wn * 16 + (lane >> 2);
    const int bfk = lane & 3;

    auto ldA = [&](int buf, int kpb) {
#pragma unroll
        for (int i = 0; i < 4; i++) {
            uint2 q0 = As[buf][afr + i * 16][kpb + afc];
            uint2 q1 = As[buf][afr + i * 16 + 8][kpb + afc];
            uint2 q2 = As[buf][afr + i * 16][kpb + afc + 4];
            uint2 q3 = As[buf][afr + i * 16 + 8][kpb + afc + 4];
            ahi[i][0] = q0.x; ahi[i][1] = q1.x; ahi[i][2] = q2.x; ahi[i][3] = q3.x;
            alo[i][0] = q0.y; alo[i][1] = q1.y; alo[i][2] = q2.y; alo[i][3] = q3.y;
        }
    };
    auto domma = [&](int buf, int kpb) {
#pragma unroll
        for (int j = 0; j < 2; j++) {
            uint2 p0 = Bs[buf][kpb + bfk][bfn + j * 8];
            uint2 p1 = Bs[buf][kpb + bfk + 4][bfn + j * 8];
#pragma unroll
            for (int i = 0; i < 4; i++) mma16(acc[i][j], ahi[i], p0.x, p1.x);
#pragma unroll
            for (int i = 0; i < 4; i++) mma16(acc[i][j], ahi[i], p0.y, p1.y);
#pragma unroll
            for (int i = 0; i < 4; i++) mma16(acc[i][j], alo[i], p0.x, p1.x);
        }
    };

    prefetchB(0, 0);
    if (!AFP32) { stageA(0, 0); }
    cp_commit();
    if (AFP32) { stageA(0, 0); }

    for (int c = 0; c < NCH; c++) {
        const int buf = c & 1;
        if (c + 1 < NCH) {
            prefetchB(c + 1, buf ^ 1);
            if (!AFP32) stageA(c + 1, buf ^ 1);
            cp_commit();
            if (AFP32) stageA(c + 1, buf ^ 1);
            cp_wait<1>();
        } else {
            cp_wait<0>();
        }
        __syncthreads();

        ldA(buf, 0);
        domma(buf, 0);
        ldA(buf, 8);
        domma(buf, 8);

        __syncthreads();
    }

    if (!FUSE) {
#pragma unroll
        for (int i = 0; i < 4; i++) {
            int r = row0 + wm * 64 + i * 16 + (lane >> 2);
#pragma unroll
            for (int j = 0; j < 2; j++) {
                int cc = col0 + wn * 16 + j * 8 + 2 * (lane & 3);
                float v0 = fmaxf(acc[i][j][0] + bias[cc],     0.f);
                float v1 = fmaxf(acc[i][j][1] + bias[cc + 1], 0.f);
                float v2 = fmaxf(acc[i][j][2] + bias[cc],     0.f);
                float v3 = fmaxf(acc[i][j][3] + bias[cc + 1], 0.f);
                C[(size_t)r * (HH / 2) + cc / 2]       = pack2(v0, v1);
                C[(size_t)(r + 8) * (HH / 2) + cc / 2] = pack2(v2, v3);
            }
        }
    } else {
        float pr[8];
#pragma unroll
        for (int ii = 0; ii < 8; ii++) pr[ii] = 0.f;
#pragma unroll
        for (int i = 0; i < 4; i++) {
#pragma unroll
            for (int j = 0; j < 2; j++) {
                int cc = col0 + wn * 16 + j * 8 + 2 * (lane & 3);
                float b0v = bias[cc], b1v = bias[cc + 1];
                float wf0 = Wf[cc],   wf1 = Wf[cc + 1];
                pr[2 * i]     += fmaxf(acc[i][j][0] + b0v, 0.f) * wf0
                               + fmaxf(acc[i][j][1] + b1v, 0.f) * wf1;
                pr[2 * i + 1] += fmaxf(acc[i][j][2] + b0v, 0.f) * wf0
                               + fmaxf(acc[i][j][3] + b1v, 0.f) * wf1;
            }
        }
#pragma unroll
        for (int ii = 0; ii < 8; ii++) {
            pr[ii] += __shfl_xor_sync(0xffffffffu, pr[ii], 1);
            pr[ii] += __shfl_xor_sync(0xffffffffu, pr[ii], 2);
        }
        if ((lane & 3) == 0) {
            int slot = blockIdx.x * 4 + wn;   // 16 slots (4 colblocks x 4 warp_n)
#pragma unroll
            for (int i = 0; i < 4; i++) {
                int r = row0 + wm * 64 + i * 16 + (lane >> 2);
                g_part[(size_t)slot * NN + r]     = pr[2 * i];
                g_part[(size_t)slot * NN + r + 8] = pr[2 * i + 1];
            }
        }
    }
}

// ---------------------------------------------------------------------------
// JAX partitionable threefry-2x32, key(42); bits = out0 ^ out1. (Validated R7.)
// ---------------------------------------------------------------------------
__device__ __forceinline__ uint32_t rotl32(uint32_t x, int d) {
    return (x << d) | (x >> (32 - d));
}

__device__ __forceinline__ float jax_uniform_u(uint32_t i)
{
    const uint32_t k0 = 0u, k1 = 42u;
    const uint32_t k2 = 0x1BD11BDAu ^ k0 ^ k1;
    uint32_t x0 = k0;
    uint32_t x1 = i + k1;
#define TF_ROUND(r) { x0 += x1; x1 = rotl32(x1, (r)) ^ x0; }
#define TF_G(a,b,c,d) TF_ROUND(a) TF_ROUND(b) TF_ROUND(c) TF_ROUND(d)
    TF_G(13, 15, 26, 6)   x0 += k1; x1 += k2 + 1u;
    TF_G(17, 29, 16, 24)  x0 += k2; x1 += k0 + 2u;
    TF_G(13, 15, 26, 6)   x0 += k0; x1 += k1 + 3u;
    TF_G(17, 29, 16, 24)  x0 += k1; x1 += k2 + 4u;
    TF_G(13, 15, 26, 6)   x0 += k2; x1 += k0 + 5u;
#undef TF_G
#undef TF_ROUND
    uint32_t bits = x0 ^ x1;
    float f = __uint_as_float((bits >> 9) | 0x3f800000u) - 1.0f;
    float u = f * (1.0f - 1e-20f) + 1e-20f;
    return fmaxf(u, 1e-20f);
}

// ---------------------------------------------------------------------------
// Per-segment softmax + Gumbel-max over the 16 logit partials.
// ---------------------------------------------------------------------------
__global__ void __launch_bounds__(SEG) final_kernel(
    const float* __restrict__ bf, float* __restrict__ out)
{
    __shared__ float red[SEG];
    __shared__ int   redi[SEG];
    __shared__ float sprob[SEG];
    __shared__ float s_sum;

    const int seg  = blockIdx.x;
    const int t    = threadIdx.x;
    const int node = seg * SEG + t;

    float s = 0.f;
#pragma unroll
    for (int k = 0; k < 16; k++) s += g_part[(size_t)k * NN + node];
    float logit = s + bf[0];
    float e = expf(logit);

    red[t] = e;
    __syncthreads();
#pragma unroll
    for (int st = SEG / 2; st > 0; st >>= 1) {
        if (t < st) red[t] += red[t + st];
        __syncthreads();
    }
    if (t == 0) s_sum = red[0];
    __syncthreads();

    float prob = e / s_sum;
    sprob[t] = prob;

    float u = jax_uniform_u((uint32_t)node);
    float g = -logf(-logf(u));
    float score = logf(prob) + g;

    red[t] = score; redi[t] = t;
    __syncthreads();
#pragma unroll
    for (int st = SEG / 2; st > 0; st >>= 1) {
        if (t < st) {
            float s2 = red[t + st]; int i2 = redi[t + st];
            if (s2 > red[t] || (s2 == red[t] && i2 > redi[t])) { red[t] = s2; redi[t] = i2; }
        }
        __syncthreads();
    }

    if (t == 0) {
        int win = redi[0];
        out[seg]            = sprob[win];
        out[BSEG + seg]     = (float)win;
        out[2 * BSEG + seg] = (float)(seg * SEG + win);
    }
}

// ---------------------------------------------------------------------------
extern "C" void kernel_launch(void* const* d_in, const int* in_sizes, int n_in,
                              void* d_out, int out_size)
{
    (void)out_size;
    const float *X, *W0, *b0, *W1, *b1, *W2, *b2, *Wf, *bf;
    if (n_in > 0 && in_sizes[0] == NN * DIN) {
        X  = (const float*)d_in[0];
        W0 = (const float*)d_in[1]; b0 = (const float*)d_in[2];
        W1 = (const float*)d_in[3]; b1 = (const float*)d_in[4];
        W2 = (const float*)d_in[5]; b2 = (const float*)d_in[6];
        Wf = (const float*)d_in[7]; bf = (const float*)d_in[8];
    } else {
        W0 = (const float*)d_in[0];
        W1 = (const float*)d_in[1];
        W2 = (const float*)d_in[2];
        Wf = (const float*)d_in[3];
        X  = (const float*)d_in[4];
        b0 = (const float*)d_in[5]; b1 = (const float*)d_in[6];
        b2 = (const float*)d_in[7]; bf = (const float*)d_in[9];
    }
    float* out = (float*)d_out;

    uint2 *hp1, *hp2, *wp0, *wp1, *wp2;
    cudaGetSymbolAddress((void**)&hp1, g_hp1);
    cudaGetSymbolAddress((void**)&hp2, g_hp2);
    cudaGetSymbolAddress((void**)&wp0, g_wp0);
    cudaGetSymbolAddress((void**)&wp1, g_wp1);
    cudaGetSymbolAddress((void**)&wp2, g_wp2);

    split_w_all<<<(W0_ELEMS + 2 * W12_ELEMS + 255) / 256, 256>>>(W0, W1, W2, wp0, wp1, wp2);

    dim3 grid(4, NN / 128);   // x fastest: 4 col-blocks share A tiles in L2
    gemm_bf16x3<DIN, true,  false><<<grid, 256>>>(X,   wp0, b0, nullptr, hp1);
    gemm_bf16x3<HH,  false, false><<<grid, 256>>>(hp1, wp1, b1, nullptr, hp2);
    gemm_bf16x3<HH,  false, true ><<<grid, 256>>>(hp2, wp2, b2, Wf, nullptr);
    final_kernel<<<BSEG, SEG>>>(bf, out);
}

// round 17
// speedup vs baseline: 1.3108x; 1.3108x over previous
#include <cuda_runtime.h>
#include <cuda_bf16.h>
#include <cstdint>

#define NN   524288
#define BSEG 4096
#define SEG  128
#define DIN  128
#define HH   256

// Static device scratch (alloc-free rules).
// Packed k-pair bf16 hi/lo: uint2 = (hi0|hi1<<16, lo0|lo1<<16)
__device__ uint2 g_hp1[(size_t)NN * (HH / 2)];
__device__ uint2 g_hp2[(size_t)NN * (HH / 2)];
__device__ float g_part[(size_t)8 * NN];          // fused logit partials
__device__ uint2 g_wp0[(size_t)(DIN / 2) * HH];   // pre-split weights
__device__ uint2 g_wp1[(size_t)(HH / 2) * HH];
__device__ uint2 g_wp2[(size_t)(HH / 2) * HH];

// ---------------------------------------------------------------------------
// bf16 two-term split: x ~= hi + lo, repr error ~2^-18 |x|.
// ---------------------------------------------------------------------------
__device__ __forceinline__ void bsplit(float x, uint32_t& h, uint32_t& l) {
    __nv_bfloat16 bh = __float2bfloat16_rn(x);
    float r = x - __bfloat162float(bh);
    __nv_bfloat16 bl = __float2bfloat16_rn(r);
    h = (uint32_t)__bfloat16_as_ushort(bh);
    l = (uint32_t)__bfloat16_as_ushort(bl);
}
__device__ __forceinline__ uint2 pack2(float x0, float x1) {
    uint32_t h0, l0, h1, l1;
    bsplit(x0, h0, l0); bsplit(x1, h1, l1);
    return make_uint2(h0 | (h1 << 16), l0 | (l1 << 16));
}

// One fused prep kernel: split W0, W1, W2 into k-pair-packed uint2 planes.
#define W0_ELEMS ((DIN / 2) * HH)
#define W12_ELEMS ((HH / 2) * HH)
__global__ void split_w_all(const float* __restrict__ W0, const float* __restrict__ W1,
                            const float* __restrict__ W2, uint2* __restrict__ o0,
                            uint2* __restrict__ o1, uint2* __restrict__ o2) {
    int idx = blockIdx.x * blockDim.x + threadIdx.x;
    const float* W; uint2* o; int rel;
    if (idx < W0_ELEMS)                 { W = W0; o = o0; rel = idx; }
    else if (idx < W0_ELEMS + W12_ELEMS){ W = W1; o = o1; rel = idx - W0_ELEMS; }
    else if (idx < W0_ELEMS + 2 * W12_ELEMS) { W = W2; o = o2; rel = idx - W0_ELEMS - W12_ELEMS; }
    else return;
    int kp = rel / HH, n = rel % HH;
    o[rel] = pack2(W[(size_t)(2 * kp) * HH + n], W[(size_t)(2 * kp + 1) * HH + n]);
}

__device__ __forceinline__ void mma16(float* c, const uint32_t* a, uint32_t b0, uint32_t b1) {
    asm volatile("mma.sync.aligned.m16n8k16.row.col.f32.bf16.bf16.f32 "
        "{%0,%1,%2,%3}, {%4,%5,%6,%7}, {%8,%9}, {%0,%1,%2,%3};"
        : "+f"(c[0]), "+f"(c[1]), "+f"(c[2]), "+f"(c[3])
        : "r"(a[0]), "r"(a[1]), "r"(a[2]), "r"(a[3]), "r"(b0), "r"(b1));
}

// cp.async helpers (16B .cg)
__device__ __forceinline__ void cp16(void* smem_dst, const void* gsrc) {
    uint32_t d = (uint32_t)__cvta_generic_to_shared(smem_dst);
    asm volatile("cp.async.cg.shared.global [%0], [%1], 16;" :: "r"(d), "l"(gsrc));
}
__device__ __forceinline__ void cp_commit() { asm volatile("cp.async.commit_group;"); }
template<int NWAIT>
__device__ __forceinline__ void cp_wait() { asm volatile("cp.async.wait_group %0;" :: "n"(NWAIT)); }

// ---------------------------------------------------------------------------
// bf16x3 tensor-core layer. Block 128x128, BK=32, 8 warps, warp tile 64x32.
// R13-best register schedule (A prefetch per kk, B double-buffered frags).
// SINGLE-barrier 2-buffer pipeline: prefetch is issued after the barrier and
// always targets the buffer the barrier just retired.
// ---------------------------------------------------------------------------
template<int HIN, bool AFP32, bool FUSE>
__global__ void __launch_bounds__(256, 2) gemm_bf16x3(
    const void* __restrict__ Ain, const uint2* __restrict__ Wp,
    const float* __restrict__ bias, const float* __restrict__ Wf,
    uint2* __restrict__ C)
{
    __shared__ uint2 As[2][128][20];   // [buf][row][kpair], pad 20 (conflict-free)
    __shared__ uint2 Bs[2][16][132];   // [buf][kpair][n],   pad 132 (conflict-free)

    const int t    = threadIdx.x;
    const int lane = t & 31;
    const int w    = t >> 5;
    const int wm   = w >> 2;
    const int wn   = w & 3;
    const int row0 = blockIdx.y * 128;
    const int col0 = blockIdx.x * 128;

    const int ar   = t >> 1;
    const int ako2 = (t & 1) * 8;
    const int bkp  = t >> 5;
    const int bn0  = (t & 31) * 4;

    constexpr int NCH = HIN / 32;

    auto prefetchB = [&](int c, int buf) {
#pragma unroll
        for (int p = 0; p < 2; p++) {
            int kp = p * 8 + bkp;
            const uint2* src = Wp + (size_t)(c * 16 + kp) * HH + col0 + bn0;
            cp16(&Bs[buf][kp][bn0],     src);
            cp16(&Bs[buf][kp][bn0 + 2], src + 2);
        }
    };
    auto stageA = [&](int c, int buf) {
        if (AFP32) {
            const float* src = (const float*)Ain + (size_t)(row0 + ar) * HIN + c * 32 + (t & 1) * 16;
#pragma unroll
            for (int q = 0; q < 4; q++) {
                float4 v = *(const float4*)(src + q * 4);
                uint2 a = pack2(v.x, v.y);
                uint2 b = pack2(v.z, v.w);
                *(uint4*)&As[buf][ar][ako2 + q * 2] = make_uint4(a.x, a.y, b.x, b.y);
            }
        } else {
            const uint2* a = (const uint2*)Ain + (size_t)(row0 + ar) * (HIN / 2) + c * 16 + ako2;
#pragma unroll
            for (int q = 0; q < 4; q++)
                cp16(&As[buf][ar][ako2 + q * 2], a + q * 2);
        }
    };

    float acc[4][4][4];
#pragma unroll
    for (int i = 0; i < 4; i++)
#pragma unroll
        for (int j = 0; j < 4; j++)
#pragma unroll
            for (int q = 0; q < 4; q++) acc[i][j][q] = 0.f;

    // A fragments single-buffered (reloaded per kk), B double-buffered
    uint32_t ahi[4][4], alo[4][4];
    uint2    bfr[2][4][2];

    const int afr = wm * 64 + (lane >> 2);
    const int afc = lane & 3;
    const int bfn = wn * 32 + (lane >> 2);
    const int bfk = lane & 3;

    auto ldA = [&](int buf, int kpb) {
#pragma unroll
        for (int i = 0; i < 4; i++) {
            uint2 q0 = As[buf][afr + i * 16][kpb + afc];
            uint2 q1 = As[buf][afr + i * 16 + 8][kpb + afc];
            uint2 q2 = As[buf][afr + i * 16][kpb + afc + 4];
            uint2 q3 = As[buf][afr + i * 16 + 8][kpb + afc + 4];
            ahi[i][0] = q0.x; ahi[i][1] = q1.x; ahi[i][2] = q2.x; ahi[i][3] = q3.x;
            alo[i][0] = q0.y; alo[i][1] = q1.y; alo[i][2] = q2.y; alo[i][3] = q3.y;
        }
    };
    auto ldB = [&](int buf, int kpb, int s) {
#pragma unroll
        for (int j = 0; j < 4; j++) {
            bfr[s][j][0] = Bs[buf][kpb + bfk][bfn + j * 8];
            bfr[s][j][1] = Bs[buf][kpb + bfk + 4][bfn + j * 8];
        }
    };
    auto domma = [&](int s) {
#pragma unroll
        for (int j = 0; j < 4; j++) {
            uint2 p0 = bfr[s][j][0];
            uint2 p1 = bfr[s][j][1];
#pragma unroll
            for (int i = 0; i < 4; i++) mma16(acc[i][j], ahi[i], p0.x, p1.x);
#pragma unroll
            for (int i = 0; i < 4; i++) mma16(acc[i][j], ahi[i], p0.y, p1.y);
#pragma unroll
            for (int i = 0; i < 4; i++) mma16(acc[i][j], alo[i], p0.x, p1.x);
        }
    };

    // Prologue: buffer 0 filled and visible to all warps.
    prefetchB(0, 0);
    if (!AFP32) { stageA(0, 0); }
    cp_commit();
    if (AFP32) { stageA(0, 0); }
    cp_wait<0>();
    __syncthreads();

    for (int c = 0; c < NCH; c++) {
        const int buf = c & 1;
        // Prefetch next chunk into the buffer retired by the last barrier.
        if (c + 1 < NCH) {
            prefetchB(c + 1, buf ^ 1);
            if (!AFP32) stageA(c + 1, buf ^ 1);
            cp_commit();
            if (AFP32) stageA(c + 1, buf ^ 1);
        }

        ldA(buf, 0);
        ldB(buf, 0, 0);
        ldB(buf, 8, 1);
        domma(0);
        ldA(buf, 8);
        domma(1);

        if (c + 1 < NCH) cp_wait<0>();
        __syncthreads();   // single barrier: next buf ready + this buf retired
    }

    if (!FUSE) {
#pragma unroll
        for (int i = 0; i < 4; i++) {
            int r = row0 + wm * 64 + i * 16 + (lane >> 2);
#pragma unroll
            for (int j = 0; j < 4; j++) {
                int cc = col0 + wn * 32 + j * 8 + 2 * (lane & 3);
                float v0 = fmaxf(acc[i][j][0] + bias[cc],     0.f);
                float v1 = fmaxf(acc[i][j][1] + bias[cc + 1], 0.f);
                float v2 = fmaxf(acc[i][j][2] + bias[cc],     0.f);
                float v3 = fmaxf(acc[i][j][3] + bias[cc + 1], 0.f);
                C[(size_t)r * (HH / 2) + cc / 2]       = pack2(v0, v1);
                C[(size_t)(r + 8) * (HH / 2) + cc / 2] = pack2(v2, v3);
            }
        }
    } else {
        float pr[8];
#pragma unroll
        for (int ii = 0; ii < 8; ii++) pr[ii] = 0.f;
#pragma unroll
        for (int i = 0; i < 4; i++) {
#pragma unroll
            for (int j = 0; j < 4; j++) {
                int cc = col0 + wn * 32 + j * 8 + 2 * (lane & 3);
                float b0v = bias[cc], b1v = bias[cc + 1];
                float wf0 = Wf[cc],   wf1 = Wf[cc + 1];
                pr[2 * i]     += fmaxf(acc[i][j][0] + b0v, 0.f) * wf0
                               + fmaxf(acc[i][j][1] + b1v, 0.f) * wf1;
                pr[2 * i + 1] += fmaxf(acc[i][j][2] + b0v, 0.f) * wf0
                               + fmaxf(acc[i][j][3] + b1v, 0.f) * wf1;
            }
        }
#pragma unroll
        for (int ii = 0; ii < 8; ii++) {
            pr[ii] += __shfl_xor_sync(0xffffffffu, pr[ii], 1);
            pr[ii] += __shfl_xor_sync(0xffffffffu, pr[ii], 2);
        }
        if ((lane & 3) == 0) {
            int slot = blockIdx.x * 4 + wn;
#pragma unroll
            for (int i = 0; i < 4; i++) {
                int r = row0 + wm * 64 + i * 16 + (lane >> 2);
                g_part[(size_t)slot * NN + r]     = pr[2 * i];
                g_part[(size_t)slot * NN + r + 8] = pr[2 * i + 1];
            }
        }
    }
}

// ---------------------------------------------------------------------------
// JAX partitionable threefry-2x32, key(42); bits = out0 ^ out1. (Validated R7.)
// ---------------------------------------------------------------------------
__device__ __forceinline__ uint32_t rotl32(uint32_t x, int d) {
    return (x << d) | (x >> (32 - d));
}

__device__ __forceinline__ float jax_uniform_u(uint32_t i)
{
    const uint32_t k0 = 0u, k1 = 42u;
    const uint32_t k2 = 0x1BD11BDAu ^ k0 ^ k1;
    uint32_t x0 = k0;
    uint32_t x1 = i + k1;
#define TF_ROUND(r) { x0 += x1; x1 = rotl32(x1, (r)) ^ x0; }
#define TF_G(a,b,c,d) TF_ROUND(a) TF_ROUND(b) TF_ROUND(c) TF_ROUND(d)
    TF_G(13, 15, 26, 6)   x0 += k1; x1 += k2 + 1u;
    TF_G(17, 29, 16, 24)  x0 += k2; x1 += k0 + 2u;
    TF_G(13, 15, 26, 6)   x0 += k0; x1 += k1 + 3u;
    TF_G(17, 29, 16, 24)  x0 += k1; x1 += k2 + 4u;
    TF_G(13, 15, 26, 6)   x0 += k2; x1 += k0 + 5u;
#undef TF_G
#undef TF_ROUND
    uint32_t bits = x0 ^ x1;
    float f = __uint_as_float((bits >> 9) | 0x3f800000u) - 1.0f;
    float u = f * (1.0f - 1e-20f) + 1e-20f;
    return fmaxf(u, 1e-20f);
}

// ---------------------------------------------------------------------------
// Per-segment softmax + Gumbel-max over the 8 logit partials.
// ---------------------------------------------------------------------------
__global__ void __launch_bounds__(SEG) final_kernel(
    const float* __restrict__ bf, float* __restrict__ out)
{
    __shared__ float red[SEG];
    __shared__ int   redi[SEG];
    __shared__ float sprob[SEG];
    __shared__ float s_sum;

    const int seg  = blockIdx.x;
    const int t    = threadIdx.x;
    const int node = seg * SEG + t;

    float s = 0.f;
#pragma unroll
    for (int k = 0; k < 8; k++) s += g_part[(size_t)k * NN + node];
    float logit = s + bf[0];
    float e = expf(logit);

    red[t] = e;
    __syncthreads();
#pragma unroll
    for (int st = SEG / 2; st > 0; st >>= 1) {
        if (t < st) red[t] += red[t + st];
        __syncthreads();
    }
    if (t == 0) s_sum = red[0];
    __syncthreads();

    float prob = e / s_sum;
    sprob[t] = prob;

    float u = jax_uniform_u((uint32_t)node);
    float g = -logf(-logf(u));
    float score = logf(prob) + g;

    red[t] = score; redi[t] = t;
    __syncthreads();
#pragma unroll
    for (int st = SEG / 2; st > 0; st >>= 1) {
        if (t < st) {
            float s2 = red[t + st]; int i2 = redi[t + st];
            if (s2 > red[t] || (s2 == red[t] && i2 > redi[t])) { red[t] = s2; redi[t] = i2; }
        }
        __syncthreads();
    }

    if (t == 0) {
        int win = redi[0];
        out[seg]            = sprob[win];
        out[BSEG + seg]     = (float)win;
        out[2 * BSEG + seg] = (float)(seg * SEG + win);
    }
}

// ---------------------------------------------------------------------------
extern "C" void kernel_launch(void* const* d_in, const int* in_sizes, int n_in,
                              void* d_out, int out_size)
{
    (void)out_size;
    const float *X, *W0, *b0, *W1, *b1, *W2, *b2, *Wf, *bf;
    if (n_in > 0 && in_sizes[0] == NN * DIN) {
        X  = (const float*)d_in[0];
        W0 = (const float*)d_in[1]; b0 = (const float*)d_in[2];
        W1 = (const float*)d_in[3]; b1 = (const float*)d_in[4];
        W2 = (const float*)d_in[5]; b2 = (const float*)d_in[6];
        Wf = (const float*)d_in[7]; bf = (const float*)d_in[8];
    } else {
        W0 = (const float*)d_in[0];
        W1 = (const float*)d_in[1];
        W2 = (const float*)d_in[2];
        Wf = (const float*)d_in[3];
        X  = (const float*)d_in[4];
        b0 = (const float*)d_in[5]; b1 = (const float*)d_in[6];
        b2 = (const float*)d_in[7]; bf = (const float*)d_in[9];
    }
    float* out = (float*)d_out;

    uint2 *hp1, *hp2, *wp0, *wp1, *wp2;
    cudaGetSymbolAddress((void**)&hp1, g_hp1);
    cudaGetSymbolAddress((void**)&hp2, g_hp2);
    cudaGetSymbolAddress((void**)&wp0, g_wp0);
    cudaGetSymbolAddress((void**)&wp1, g_wp1);
    cudaGetSymbolAddress((void**)&wp2, g_wp2);

    split_w_all<<<(W0_ELEMS + 2 * W12_ELEMS + 255) / 256, 256>>>(W0, W1, W2, wp0, wp1, wp2);

    dim3 grid(2, NN / 128);
    gemm_bf16x3<DIN, true,  false><<<grid, 256>>>(X,   wp0, b0, nullptr, hp1);
    gemm_bf16x3<HH,  false, false><<<grid, 256>>>(hp1, wp1, b1, nullptr, hp2);
    gemm_bf16x3<HH,  false, true ><<<grid, 256>>>(hp2, wp2, b2, Wf, nullptr);
    final_kernel<<<BSEG, SEG>>>(bf, out);
}